// round 7
// baseline (speedup 1.0000x reference)
#include <cuda_runtime.h>
#include <math.h>

#define T_  512
#define B_  2048
#define I_  24
#define H_  20

// Scratch xg, TRANSPOSED layout: xg[t][u][b] = float4(i,f,g,o) for unit u.
// At fixed (t,u), b is contiguous -> xg stores are fully coalesced.
// One pad timestep for the recur prefetch.
__device__ float4 g_xg[(size_t)(T_ + 1) * H_ * B_];
// h[t*B+b][u] for the head pass.
__device__ float  g_h[(size_t)T_ * B_ * H_];

__device__ __forceinline__ float tanhx(float x) {
    float r; asm("tanh.approx.f32 %0,%1;" : "=f"(r) : "f"(x)); return r;
}
__device__ __forceinline__ float sigx(float x) {   // sigmoid via HW tanh
    return fmaf(0.5f, tanhx(0.5f * x), 0.5f);
}

// ---------------------------------------------------------------------------
// Kernel 1: xg = x @ W_ih^T + (b_ih+b_hh) for t < len[b].
// Two tokens per thread (bA = b0+tid, bB = bA+128). Weights staged in shared
// transposed to wsh[grp][k][4*ul+gate]; float4 accumulators hold (i,f,g,o)
// of unit grp*5+j and store COALESCED into g_xg[t][u][b].
// ---------------------------------------------------------------------------
#define XG_TPB 128
__global__ __launch_bounds__(XG_TPB, 4)
void xg_kernel(const float* __restrict__ x,
               const int*   __restrict__ lens,
               const float* __restrict__ Wih,
               const float* __restrict__ bih,
               const float* __restrict__ bhh)
{
    __shared__ float wsh[4][I_][20];   // [unit-group][k][4*ul+gate]
    __shared__ float bsh[4][20];

    const int t  = blockIdx.x >> 3;               // 8 chunks of 256 b per t
    const int b0 = (blockIdx.x & 7) * 256;
    if (t >= lens[b0]) return;                    // whole chunk masked

    const int tid = threadIdx.x;
    for (int idx = tid; idx < 4 * I_ * 20; idx += XG_TPB) {
        int r = idx % 20, k = (idx / 20) % I_, grp = idx / (20 * I_);
        int u = grp * 5 + (r >> 2), gate = r & 3;
        wsh[grp][k][r] = Wih[(gate * H_ + u) * I_ + k];
    }
    if (tid < 80) {
        int r = tid % 20, grp = tid / 20;
        int u = grp * 5 + (r >> 2), gate = r & 3;
        bsh[grp][r] = bih[gate * H_ + u] + bhh[gate * H_ + u];
    }
    __syncthreads();

    const int bA = b0 + tid;
    const int bB = bA + 128;
    const bool actB = (t < lens[bB]);             // actB => actA (sorted desc)
    if (t >= lens[bA]) return;                    // no barriers after this

    float xA[I_], xB[I_];
    {
        const float4* pA = (const float4*)(x + ((size_t)t * B_ + bA) * I_);
        const float4* pB = (const float4*)(x + ((size_t)t * B_ + bB) * I_);
        #pragma unroll
        for (int q = 0; q < 6; q++) {
            float4 v = pA[q];
            xA[q*4+0]=v.x; xA[q*4+1]=v.y; xA[q*4+2]=v.z; xA[q*4+3]=v.w;
            float4 w = pB[q];
            xB[q*4+0]=w.x; xB[q*4+1]=w.y; xB[q*4+2]=w.z; xB[q*4+3]=w.w;
        }
    }

    float4* outt = g_xg + (size_t)t * H_ * B_;    // row base for this t

    #pragma unroll 1
    for (int grp = 0; grp < 4; grp++) {
        float4 a[5], b4[5];
        const float4* bq = (const float4*)bsh[grp];
        #pragma unroll
        for (int j = 0; j < 5; j++) { a[j] = bq[j]; b4[j] = bq[j]; }

        #pragma unroll 8
        for (int k = 0; k < I_; k++) {
            const float ka = xA[k], kb = xB[k];
            const float4* wp = (const float4*)&wsh[grp][k][0];
            #pragma unroll
            for (int j = 0; j < 5; j++) {
                float4 w = wp[j];
                a[j].x  = fmaf(w.x, ka, a[j].x);
                a[j].y  = fmaf(w.y, ka, a[j].y);
                a[j].z  = fmaf(w.z, ka, a[j].z);
                a[j].w  = fmaf(w.w, ka, a[j].w);
                b4[j].x = fmaf(w.x, kb, b4[j].x);
                b4[j].y = fmaf(w.y, kb, b4[j].y);
                b4[j].z = fmaf(w.z, kb, b4[j].z);
                b4[j].w = fmaf(w.w, kb, b4[j].w);
            }
        }
        #pragma unroll
        for (int j = 0; j < 5; j++) {
            float4* row = outt + (size_t)(grp * 5 + j) * B_;   // unit row
            row[bA] = a[j];                 // coalesced across the warp
            if (actB) row[bB] = b4[j];
        }
    }
}

// ---------------------------------------------------------------------------
// Kernel 2: recurrence, one warp per batch element, t < len[b] only.
// h broadcast via SHFL, Whh in registers. Per-step gate load is now 20
// scattered 16B reads (transposed layout) but prefetched one step ahead.
// ---------------------------------------------------------------------------
__global__ __launch_bounds__(128, 4)
void recur_kernel(const int*   __restrict__ lens,
                  const float* __restrict__ Whh)
{
    const int lane = threadIdx.x & 31;
    const int wid  = threadIdx.x >> 5;
    const int j    = blockIdx.x;
    const int b    = (wid < 2) ? (2*j + wid) : (2047 - 2*j - (wid - 2));
    const int uu   = (lane < H_) ? lane : 0;      // lanes 20..31 mirror u=0

    float wi[H_], wf[H_], wg[H_], wo[H_];
    #pragma unroll
    for (int k = 0; k < H_; k++) {
        wi[k] = Whh[(0*H_ + uu) * H_ + k];
        wf[k] = Whh[(1*H_ + uu) * H_ + k];
        wg[k] = Whh[(2*H_ + uu) * H_ + k];
        wo[k] = Whh[(3*H_ + uu) * H_ + k];
    }
    const int mylen = lens[b];                    // >= 1

    float h = 0.0f, c = 0.0f;

    const float4* xp = g_xg + (size_t)uu * B_ + b;   // (t=0, uu, b)
    const size_t  xstride = (size_t)H_ * B_;          // per-t stride (float4s)
    float4 xg = *xp;
    xp += xstride;

    float* hp = &g_h[(size_t)b * H_ + lane];

    for (int t = 0; t < mylen; t++) {
        float4 nxt = *xp;                         // row t+1 <= 512 (padded)
        xp += xstride;

        float ai = xg.x, af = xg.y, ag = xg.z, ao = xg.w;
        #pragma unroll
        for (int k = 0; k < H_; k++) {
            float hk = __shfl_sync(0xffffffffu, h, k);
            ai = fmaf(wi[k], hk, ai);
            af = fmaf(wf[k], hk, af);
            ag = fmaf(wg[k], hk, ag);
            ao = fmaf(wo[k], hk, ao);
        }

        c = fmaf(sigx(af), c, sigx(ai) * tanhx(ag));
        h = sigx(ao) * tanhx(c);

        if (lane < H_) hp[(size_t)t * (B_ * H_)] = h;
        xg = nxt;
    }
}

// ---------------------------------------------------------------------------
// Kernel 3: heads + padding over the full [T, B] grid.
// ---------------------------------------------------------------------------
__global__ __launch_bounds__(256)
void head_kernel(const int*   __restrict__ lens,
                 const float* __restrict__ Wa,
                 const float* __restrict__ ba,
                 const float* __restrict__ Wb,
                 const float* __restrict__ bb,
                 float* __restrict__ out)
{
    const int idx = blockIdx.x * 256 + threadIdx.x;   // t*B + b
    const int b   = idx & (B_ - 1);
    const int t   = idx >> 11;

    float za = ba[0], zb = bb[0];
    if (t < lens[b]) {
        float4 hq[5];
        const float4* hp = (const float4*)&g_h[(size_t)idx * H_];
        #pragma unroll
        for (int q = 0; q < 5; q++) hq[q] = hp[q];
        const float* hv = (const float*)hq;
        #pragma unroll
        for (int k = 0; k < H_; k++) {
            za = fmaf(hv[k], Wa[k], za);
            zb = fmaf(hv[k], Wb[k], zb);
        }
    }
    out[idx] = __expf(za);
    out[(size_t)T_ * B_ + idx] =
        fmaxf(zb, 0.0f) + __logf(1.0f + __expf(-fabsf(zb)));
}

extern "C" void kernel_launch(void* const* d_in, const int* in_sizes, int n_in,
                              void* d_out, int out_size)
{
    const float *x = 0, *Wih = 0, *Whh = 0, *bih = 0, *bhh = 0;
    const float *Wa = 0, *ba = 0, *Wb = 0, *bb = 0;
    const int *lens = 0;
    int seen80 = 0, seen20 = 0, seen1 = 0;
    for (int i = 0; i < n_in; i++) {
        int s = in_sizes[i];
        if      (s == T_ * B_ * I_) x    = (const float*)d_in[i];
        else if (s == B_)           lens = (const int*)d_in[i];
        else if (s == 4*H_ * I_)    Wih  = (const float*)d_in[i];
        else if (s == 4*H_ * H_)    Whh  = (const float*)d_in[i];
        else if (s == 4*H_) { if (seen80++ == 0) bih = (const float*)d_in[i]; else bhh = (const float*)d_in[i]; }
        else if (s == H_)   { if (seen20++ == 0) Wa  = (const float*)d_in[i]; else Wb  = (const float*)d_in[i]; }
        else if (s == 1)    { if (seen1++  == 0) ba  = (const float*)d_in[i]; else bb  = (const float*)d_in[i]; }
    }

    float* out = (float*)d_out;
    xg_kernel<<<T_ * 8, XG_TPB>>>(x, lens, Wih, bih, bhh);
    recur_kernel<<<512, 128>>>(lens, Whh);
    head_kernel<<<(T_ * B_) / 256, 256>>>(lens, Wa, ba, Wb, bb, out);
}